// round 12
// baseline (speedup 1.0000x reference)
#include <cuda_runtime.h>
#include <math.h>
#include <stdint.h>

#define Bq 256
#define Sq 512
#define Iq 128
#define Hq 256
#define CPG 16      // CTAs per group
#define NGRP 8      // groups
#define GB 32       // batches per group
#define NCTA 128
#define NTHR 1024

typedef unsigned long long u64;

// ---- global scratch ----
__device__ float d_enc[(size_t)Sq * Bq * Hq];   // [S][B][H], read-once addresses in loop
__device__ float d_scores[Bq * Iq];             // reused every step -> L1-bypass access
__device__ int   g_cnt[NGRP];
__device__ int   g_phase[NGRP];

// ------------------------------- helpers -----------------------------------
__device__ __forceinline__ int ld_acq(const int* p) {
    int v;
    asm volatile("ld.acquire.gpu.b32 %0, [%1];" : "=r"(v) : "l"(p) : "memory");
    return v;
}
__device__ __forceinline__ int atom_add_release(int* p, int v) {
    int old;
    asm volatile("atom.release.gpu.global.add.s32 %0, [%1], %2;"
                 : "=r"(old) : "l"(p), "r"(v) : "memory");
    return old;
}
__device__ __forceinline__ void red_release_add(int* p, int v) {
    asm volatile("red.release.gpu.global.add.s32 [%0], %1;" :: "l"(p), "r"(v) : "memory");
}
__device__ __forceinline__ void st_relaxed(int* p, int v) {
    asm volatile("st.relaxed.gpu.global.s32 [%0], %1;" :: "l"(p), "r"(v) : "memory");
}
__device__ __forceinline__ void fma2(u64& d, u64 a, u64 b) {
    asm("fma.rn.f32x2 %0, %1, %2, %0;" : "+l"(d) : "l"(a), "l"(b));
}
__device__ __forceinline__ float f2sum(u64 a, float bias) {
    float lo, hi;
    asm("mov.b64 {%0,%1}, %2;" : "=f"(lo), "=f"(hi) : "l"(a));
    return lo + hi + bias;
}
__device__ __forceinline__ float fsig(float x)  { return 1.f / (1.f + __expf(-x)); }
__device__ __forceinline__ float ftanh(float x) { return 1.f - 2.f / (__expf(2.f * x) + 1.f); }

// Fence-free group barrier (validated R11): release-atomic arrival, acquire-poll.
__device__ __forceinline__ void group_barrier(int g, int& want) {
    __syncthreads();
    if (threadIdx.x == 0) {
        want++;
        int old = atom_add_release(&g_cnt[g], 1);
        if (old == CPG - 1) {
            st_relaxed(&g_cnt[g], 0);
            red_release_add(&g_phase[g], 1);
        } else {
            while (ld_acq(&g_phase[g]) < want) { }
        }
    }
    __syncthreads();
}

// SMEM layout offsets (floats)
#define O_WA   0        // 8*384   = 3072
#define O_WIH  3072     // 48*128  = 6144
#define O_WHH  9216     // 48*256  = 12288
#define O_BA   21504    // 8
#define O_BIH  21512    // 48
#define O_BHH  21560    // 48
#define O_HS   21608    // paired h: (k,b)->((k>>1)*33+b)*2+(k&1)   8448
#define O_XTS  30056    // 4224
#define O_XWS  34280    // 4224
#define O_GIS  38504    // 48*33 = 1584
#define O_GHS  40088    // 1584 (also prt[1024] in tail)
#define O_RED  41672    // 32
#define SMEM_FLOATS 41704

extern "C" __global__ void __launch_bounds__(NTHR)
da_rnn_kernel(const float* __restrict__ x,
              const float* __restrict__ W_a,  const float* __restrict__ b_a,
              const float* __restrict__ W_ih, const float* __restrict__ b_ih,
              const float* __restrict__ W_hh, const float* __restrict__ b_hh,
              const float* __restrict__ W_t,  const float* __restrict__ b_t,
              const float* __restrict__ W_f,  const float* __restrict__ b_f,
              float* __restrict__ out)
{
    extern __shared__ float sm[];
    float* Wa_s  = sm + O_WA;
    float* Wih_s = sm + O_WIH;
    float* Whh_s = sm + O_WHH;
    float* ba_s  = sm + O_BA;
    float* bih_s = sm + O_BIH;
    float* bhh_s = sm + O_BHH;
    float* hsf   = sm + O_HS;
    float* xtf   = sm + O_XTS;
    float* xwf   = sm + O_XWS;
    float* gis   = sm + O_GIS;
    float* ghs   = sm + O_GHS;
    float* red   = sm + O_RED;
    const u64* hs64 = (const u64*)hsf;
    const u64* xt64 = (const u64*)xtf;
    const u64* xw64 = (const u64*)xwf;

    const int tid  = threadIdx.x;
    const int grp  = blockIdx.x >> 4;
    const int rr   = blockIdx.x & 15;
    const int gb0  = grp * GB;
    const int lane = tid & 31;
    const int wrp  = tid >> 5;            // 0..31

    // ---- load weight slice into SMEM (once) ----
    for (int i = tid; i < 8 * 384; i += NTHR)
        Wa_s[i] = W_a[3072 * rr + i];
    for (int i = tid; i < 48 * 128; i += NTHR) {
        int l = i >> 7, k = i & 127;
        int grow = (l >> 4) * Hq + 16 * rr + (l & 15);
        Wih_s[i] = W_ih[grow * Iq + k];
    }
    for (int i = tid; i < 48 * 256; i += NTHR) {
        int l = i >> 8, k = i & 255;
        int grow = (l >> 4) * Hq + 16 * rr + (l & 15);
        Whh_s[i] = W_hh[grow * Hq + k];
    }
    if (tid < 8) ba_s[tid] = b_a[8 * rr + tid];
    if (tid < 48) {
        int grow = (tid >> 4) * Hq + 16 * rr + (tid & 15);
        bih_s[tid] = b_ih[grow];
        bhh_s[tid] = b_hh[grow];
    }

    int want = 0;
    if (tid == 0) want = ld_acq(&g_phase[grp]);

    // ---- x pipeline: thread owns (batch pb, k-range pk..pk+3) ----
    const int pb = tid >> 5;            // 0..31
    const int pk = (tid & 31) * 4;      // 0..124
    const float* xrow = x + ((size_t)(gb0 + pb) * Sq) * Iq + pk;

    // prologue: xtf <- x(0); px <- x(1)
    {
        float4 a0 = *(const float4*)(xrow);
        float2 p0; p0.x = a0.x; p0.y = a0.y;
        float2 p1; p1.x = a0.z; p1.y = a0.w;
        ((float2*)xtf)[((pk >> 1) + 0) * 33 + pb] = p0;
        ((float2*)xtf)[((pk >> 1) + 1) * 33 + pb] = p1;
    }
    float4 pxa = *(const float4*)(xrow + (size_t)Iq);

    // ================= recurrent loop =================
    for (int t = 0; t < Sq; t++) {
        // ---- stage h(t-1) into paired SMEM ----
        if (t == 0) {
            for (int i = tid; i < Hq * GB; i += NTHR) {
                int b = i >> 8, u = i & 255;
                hsf[((u >> 1) * 33 + b) * 2 + (u & 1)] = 0.f;
            }
        } else {
            const int b2 = tid >> 5;            // 0..31
            const int u0 = (tid & 31) * 8;      // 0..248
            const float* ep = d_enc + (size_t)(t - 1) * Bq * Hq + (size_t)(gb0 + b2) * Hq + u0;
            float4 h0 = *(const float4*)(ep);
            float4 h1 = *(const float4*)(ep + 4);
            const float hv[8] = {h0.x,h0.y,h0.z,h0.w, h1.x,h1.y,h1.z,h1.w};
            #pragma unroll
            for (int j = 0; j < 4; j++) {
                float2 p; p.x = hv[2 * j]; p.y = hv[2 * j + 1];
                ((float2*)hsf)[((u0 >> 1) + j) * 33 + b2] = p;
            }
        }
        __syncthreads();

        // ---- P1: warps 0-7 score rows; warps 8-31 two gh rows each ----
        if (wrp < 8) {
            const int srow = wrp;
            const u64* wax = (const u64*)(Wa_s + srow * 384);
            u64 sacc = 0ull;
            #pragma unroll 4
            for (int k2 = 0; k2 < 64; k2 += 2) {
                u64 x0 = xt64[k2 * 33 + lane];
                u64 x1 = xt64[(k2 + 1) * 33 + lane];
                ulonglong2 w = *(const ulonglong2*)(wax + k2);
                fma2(sacc, w.x, x0); fma2(sacc, w.y, x1);
            }
            const u64* wah = wax + 64;
            #pragma unroll 4
            for (int k2 = 0; k2 < 128; k2 += 2) {
                u64 h0 = hs64[k2 * 33 + lane];
                u64 h1 = hs64[(k2 + 1) * 33 + lane];
                ulonglong2 wa = *(const ulonglong2*)(wah + k2);
                fma2(sacc, wa.x, h0); fma2(sacc, wa.y, h1);
            }
            __stcg(&d_scores[(gb0 + lane) * Iq + 8 * rr + srow],
                   ftanh(f2sum(sacc, ba_s[srow])));
        } else {
            const int R = 2 * (wrp - 8);        // 0..46
            const u64* w0 = (const u64*)(Whh_s + R * Hq);
            const u64* w1 = w0 + 128;
            u64 a0 = 0ull, a1 = 0ull;
            #pragma unroll 4
            for (int k2 = 0; k2 < 128; k2 += 2) {
                u64 h0 = hs64[k2 * 33 + lane];
                u64 h1 = hs64[(k2 + 1) * 33 + lane];
                ulonglong2 v0 = *(const ulonglong2*)(w0 + k2);
                fma2(a0, v0.x, h0); fma2(a0, v0.y, h1);
                ulonglong2 v1 = *(const ulonglong2*)(w1 + k2);
                fma2(a1, v1.x, h0); fma2(a1, v1.y, h1);
            }
            ghs[R * 33 + lane]       = f2sum(a0, bhh_s[R]);
            ghs[(R + 1) * 33 + lane] = f2sum(a1, bhh_s[R + 1]);
        }
        group_barrier(grp, want);   // scores visible group-wide

        // ---- P2: softmax + xw, 1 batch per warp ----
        {
            const int b = wrp;
            const float* sp = d_scores + (size_t)(gb0 + b) * Iq;
            float e0 = __expf(__ldcg(sp + lane));
            float e1 = __expf(__ldcg(sp + lane + 32));
            float e2 = __expf(__ldcg(sp + lane + 64));
            float e3 = __expf(__ldcg(sp + lane + 96));
            float s = e0 + e1 + e2 + e3;
            #pragma unroll
            for (int off = 16; off; off >>= 1) s += __shfl_xor_sync(0xffffffffu, s, off);
            float inv = 1.f / s;
            int k = lane;
            xwf[((k >> 1) * 33 + b) * 2 + (k & 1)] = e0 * inv * xtf[((k >> 1) * 33 + b) * 2 + (k & 1)];
            k = lane + 32;
            xwf[((k >> 1) * 33 + b) * 2 + (k & 1)] = e1 * inv * xtf[((k >> 1) * 33 + b) * 2 + (k & 1)];
            k = lane + 64;
            xwf[((k >> 1) * 33 + b) * 2 + (k & 1)] = e2 * inv * xtf[((k >> 1) * 33 + b) * 2 + (k & 1)];
            k = lane + 96;
            xwf[((k >> 1) * 33 + b) * 2 + (k & 1)] = e3 * inv * xtf[((k >> 1) * 33 + b) * 2 + (k & 1)];
        }
        __syncthreads();   // xw ready; all xtf(t) reads complete

        // ---- commit prefetched x(t+1); prefetch x(t+2) ----
        if (t + 1 < Sq) {
            float2 p0; p0.x = pxa.x; p0.y = pxa.y;
            float2 p1; p1.x = pxa.z; p1.y = pxa.w;
            ((float2*)xtf)[((pk >> 1) + 0) * 33 + pb] = p0;
            ((float2*)xtf)[((pk >> 1) + 1) * 33 + pb] = p1;
            if (t + 2 < Sq)
                pxa = *(const float4*)(xrow + (size_t)(t + 2) * Iq);
        }

        // ---- P3: gi, warps 0-23 x 2 rows ----
        if (wrp < 24) {
            const int R = 2 * wrp;
            const u64* w0 = (const u64*)(Wih_s + R * Iq);
            const u64* w1 = w0 + 64;
            u64 a0 = 0ull, a1 = 0ull;
            #pragma unroll 4
            for (int k2 = 0; k2 < 64; k2 += 2) {
                u64 x0 = xw64[k2 * 33 + lane];
                u64 x1 = xw64[(k2 + 1) * 33 + lane];
                ulonglong2 v0 = *(const ulonglong2*)(w0 + k2);
                fma2(a0, v0.x, x0); fma2(a0, v0.y, x1);
                ulonglong2 v1 = *(const ulonglong2*)(w1 + k2);
                fma2(a1, v1.x, x0); fma2(a1, v1.y, x1);
            }
            gis[R * 33 + lane]       = f2sum(a0, bih_s[R]);
            gis[(R + 1) * 33 + lane] = f2sum(a1, bih_s[R + 1]);
        }
        __syncthreads();

        // ---- gates + h_new (512 work items) ----
        if (tid < 512) {
            int u = tid & 15;
            int b = tid >> 4;
            float r = fsig(gis[u * 33 + b] + ghs[u * 33 + b]);
            float z = fsig(gis[(16 + u) * 33 + b] + ghs[(16 + u) * 33 + b]);
            float n = ftanh(gis[(32 + u) * 33 + b] + r * ghs[(32 + u) * 33 + b]);
            int ug = 16 * rr + u;
            float hp = hsf[((ug >> 1) * 33 + b) * 2 + (ug & 1)];
            float hn = (1.f - z) * n + z * hp;
            d_enc[((size_t)t * Bq + gb0 + b) * Hq + ug] = hn;
        }
        group_barrier(grp, want);   // h(t) visible group-wide
    }

    // ================= temporal attention + FC (2 batches/CTA) =================
    float* wts = xtf;     // 256 floats
    float* ess = gis;     // 512 floats
    float* prt = ghs;     // 1024 floats (fits: 1584)
    if (tid < Hq) wts[tid] = W_t[tid];
    const float btv = b_t[0];
    const float bfv = b_f[0];
    __syncthreads();

    for (int bi = 0; bi < 2; bi++) {
        int bb = gb0 + 2 * rr + bi;

        // es[t] = exp(tanh(enc . W_t + b_t)), warp per t-strip (32 warps)
        for (int tt = wrp; tt < Sq; tt += 32) {
            const float* er = d_enc + ((size_t)tt * Bq + bb) * Hq;
            float s = 0.f;
            #pragma unroll
            for (int j = 0; j < 8; j++) s += er[lane + 32 * j] * wts[lane + 32 * j];
            #pragma unroll
            for (int off = 16; off; off >>= 1) s += __shfl_xor_sync(0xffffffffu, s, off);
            if (lane == 0) ess[tt] = __expf(ftanh(s + btv));
        }
        __syncthreads();

        // denom over 512 entries (warps 0-15 carry data)
        float pp = (tid < 512) ? ess[tid] : 0.f;
        #pragma unroll
        for (int off = 16; off; off >>= 1) pp += __shfl_xor_sync(0xffffffffu, pp, off);
        if (lane == 0 && wrp < 16) red[wrp] = pp;
        __syncthreads();
        float denom = 0.f;
        #pragma unroll
        for (int j = 0; j < 16; j++) denom += red[j];

        // context partials: 4-way t-split, 128 t's per thread
        {
            int h = tid & 255, q = tid >> 8;    // q = 0..3
            const float* eb = d_enc + ((size_t)(q * 128) * Bq + bb) * Hq + h;
            const float* ep = ess + q * 128;
            float acc = 0.f;
            #pragma unroll 4
            for (int tt = 0; tt < 128; tt++)
                acc += ep[tt] * eb[(size_t)tt * Bq * Hq];
            prt[tid] = acc;
        }
        __syncthreads();

        if (tid < Hq) {
            float ctx = (prt[tid] + prt[tid + 256] + prt[tid + 512] + prt[tid + 768]) / denom;
            float part = ctx * W_f[tid];
            #pragma unroll
            for (int off = 16; off; off >>= 1) part += __shfl_xor_sync(0xffffffffu, part, off);
            if (lane == 0) red[16 + wrp] = part;
        }
        __syncthreads();
        if (tid == 0) {
            float lg = bfv;
            #pragma unroll
            for (int j = 0; j < 8; j++) lg += red[16 + j];
            out[bb] = 1.f / (1.f + __expf(-lg));
        }
        __syncthreads();
    }
}

extern "C" void kernel_launch(void* const* d_in, const int* in_sizes, int n_in,
                              void* d_out, int out_size)
{
    const float* x    = (const float*)d_in[0];
    const float* W_a  = (const float*)d_in[1];
    const float* b_a  = (const float*)d_in[2];
    const float* W_ih = (const float*)d_in[3];
    const float* b_ih = (const float*)d_in[4];
    const float* W_hh = (const float*)d_in[5];
    const float* b_hh = (const float*)d_in[6];
    const float* W_t  = (const float*)d_in[7];
    const float* b_t  = (const float*)d_in[8];
    const float* W_f  = (const float*)d_in[9];
    const float* b_f  = (const float*)d_in[10];

    const size_t smem_bytes = (size_t)SMEM_FLOATS * sizeof(float);   // 166816
    cudaFuncSetAttribute(da_rnn_kernel, cudaFuncAttributeMaxDynamicSharedMemorySize,
                         (int)smem_bytes);
    da_rnn_kernel<<<NCTA, NTHR, smem_bytes>>>(x, W_a, b_a, W_ih, b_ih, W_hh, b_hh,
                                              W_t, b_t, W_f, b_f, (float*)d_out);
}

// round 13
// speedup vs baseline: 1.1566x; 1.1566x over previous
#include <cuda_runtime.h>
#include <math.h>
#include <stdint.h>

#define Bq 256
#define Sq 512
#define Iq 128
#define Hq 256
#define CPG 16      // CTAs per group
#define NGRP 8      // groups
#define GB 32       // batches per group
#define NCTA 128
#define NTHR 512

typedef unsigned long long u64;

// ---- global scratch ----
__device__ float d_enc[(size_t)Sq * Bq * Hq];   // [S][B][H], read-once addresses in loop
__device__ float d_scores[Bq * Iq];             // reused every step -> L1-bypass access
__device__ int   g_cnt[NGRP];
__device__ int   g_phase[NGRP];

// ------------------------------- helpers -----------------------------------
__device__ __forceinline__ int ld_acq(const int* p) {
    int v;
    asm volatile("ld.acquire.gpu.b32 %0, [%1];" : "=r"(v) : "l"(p) : "memory");
    return v;
}
__device__ __forceinline__ int atom_add_release(int* p, int v) {
    int old;
    asm volatile("atom.release.gpu.global.add.s32 %0, [%1], %2;"
                 : "=r"(old) : "l"(p), "r"(v) : "memory");
    return old;
}
__device__ __forceinline__ void red_release_add(int* p, int v) {
    asm volatile("red.release.gpu.global.add.s32 [%0], %1;" :: "l"(p), "r"(v) : "memory");
}
__device__ __forceinline__ void st_relaxed(int* p, int v) {
    asm volatile("st.relaxed.gpu.global.s32 [%0], %1;" :: "l"(p), "r"(v) : "memory");
}
__device__ __forceinline__ void fma2(u64& d, u64 a, u64 b) {
    asm("fma.rn.f32x2 %0, %1, %2, %0;" : "+l"(d) : "l"(a), "l"(b));
}
__device__ __forceinline__ float f2sum(u64 a, float bias) {
    float lo, hi;
    asm("mov.b64 {%0,%1}, %2;" : "=f"(lo), "=f"(hi) : "l"(a));
    return lo + hi + bias;
}
__device__ __forceinline__ float fsig(float x)  { return 1.f / (1.f + __expf(-x)); }
__device__ __forceinline__ float ftanh(float x) { return 1.f - 2.f / (__expf(2.f * x) + 1.f); }

// Fence-free group barrier (validated R11): release-atomic arrival, acquire-poll.
__device__ __forceinline__ void group_barrier(int g, int& want) {
    __syncthreads();
    if (threadIdx.x == 0) {
        want++;
        int old = atom_add_release(&g_cnt[g], 1);
        if (old == CPG - 1) {
            st_relaxed(&g_cnt[g], 0);
            red_release_add(&g_phase[g], 1);
        } else {
            while (ld_acq(&g_phase[g]) < want) { }
        }
    }
    __syncthreads();
}

// SMEM layout offsets (floats). Weight rows carry a 4-float mid-pad so the two
// half-warps (K-split) read bank-disjoint 16B words.
#define O_WAX  0        // 8 rows * 132 = 1056   W_a x-part [64|pad4|64]
#define O_WAH  1056     // 8 rows * 260 = 2080   W_a h-part [128|pad4|128]
#define O_WIH  3136     // 48 rows * 132 = 6336
#define O_WHH  9472     // 48 rows * 260 = 12480
#define O_BA   21952    // 8
#define O_BIH  21960    // 48
#define O_BHH  22008    // 48
#define O_HS   22056    // paired h: (k,b)->((k>>1)*33+b)*2+(k&1)   8448
#define O_XTS  30504    // 4224
#define O_XWS  34728    // 4224
#define O_GIS  38952    // 48*33 = 1584
#define O_GHS  40536    // 1584
#define O_RED  42120    // 32
#define SMEM_FLOATS 42152      // 168,608 bytes

extern "C" __global__ void __launch_bounds__(NTHR)
da_rnn_kernel(const float* __restrict__ x,
              const float* __restrict__ W_a,  const float* __restrict__ b_a,
              const float* __restrict__ W_ih, const float* __restrict__ b_ih,
              const float* __restrict__ W_hh, const float* __restrict__ b_hh,
              const float* __restrict__ W_t,  const float* __restrict__ b_t,
              const float* __restrict__ W_f,  const float* __restrict__ b_f,
              float* __restrict__ out)
{
    extern __shared__ float sm[];
    float* Wax_s = sm + O_WAX;
    float* Wah_s = sm + O_WAH;
    float* Wih_s = sm + O_WIH;
    float* Whh_s = sm + O_WHH;
    float* ba_s  = sm + O_BA;
    float* bih_s = sm + O_BIH;
    float* bhh_s = sm + O_BHH;
    float* hsf   = sm + O_HS;
    float* xtf   = sm + O_XTS;
    float* xwf   = sm + O_XWS;
    float* gis   = sm + O_GIS;
    float* ghs   = sm + O_GHS;
    float* red   = sm + O_RED;
    const u64* hs64 = (const u64*)hsf;   // [k2*33 + b]
    const u64* xt64 = (const u64*)xtf;
    const u64* xw64 = (const u64*)xwf;

    const int tid  = threadIdx.x;
    const int grp  = blockIdx.x >> 4;
    const int rr   = blockIdx.x & 15;
    const int gb0  = grp * GB;
    const int lane = tid & 31;
    const int wrp  = tid >> 5;            // 0..15
    const int sub  = lane >> 4;           // K-half
    const int bl   = lane & 15;           // batch-in-half
    const int bh   = wrp & 1;             // batch half
    const int rg   = wrp >> 1;            // row group 0..7
    const int bb1  = bh * 16 + bl;        // this lane's batch 0..31

    // ---- load weight slice into SMEM (once, padded layout) ----
    for (int i = tid; i < 8 * 128; i += NTHR) {
        int r = i >> 7, kk = i & 127;
        Wax_s[r * 132 + kk + (kk >= 64 ? 4 : 0)] = W_a[(8 * rr + r) * 384 + kk];
    }
    for (int i = tid; i < 8 * 256; i += NTHR) {
        int r = i >> 8, kk = i & 255;
        Wah_s[r * 260 + kk + (kk >= 128 ? 4 : 0)] = W_a[(8 * rr + r) * 384 + 128 + kk];
    }
    for (int i = tid; i < 48 * 128; i += NTHR) {
        int l = i >> 7, k = i & 127;
        int grow = (l >> 4) * Hq + 16 * rr + (l & 15);
        Wih_s[l * 132 + k + (k >= 64 ? 4 : 0)] = W_ih[grow * Iq + k];
    }
    for (int i = tid; i < 48 * 256; i += NTHR) {
        int l = i >> 8, k = i & 255;
        int grow = (l >> 4) * Hq + 16 * rr + (l & 15);
        Whh_s[l * 260 + k + (k >= 128 ? 4 : 0)] = W_hh[grow * Hq + k];
    }
    if (tid < 8) ba_s[tid] = b_a[8 * rr + tid];
    if (tid < 48) {
        int grow = (tid >> 4) * Hq + 16 * rr + (tid & 15);
        bih_s[tid] = b_ih[grow];
        bhh_s[tid] = b_hh[grow];
    }

    int want = 0;
    if (tid == 0) want = ld_acq(&g_phase[grp]);

    // ---- x pipeline: thread owns (batch pb, k-range pk..pk+7) ----
    const int pb = tid >> 4;            // 0..31
    const int pk = (tid & 15) * 8;      // 0..120
    const float* xrow = x + ((size_t)(gb0 + pb) * Sq) * Iq + pk;

    // prologue: xtf <- x(0); px <- x(1)
    {
        float4 a0 = *(const float4*)(xrow);
        float4 a1 = *(const float4*)(xrow + 4);
        const float v[8] = {a0.x, a0.y, a0.z, a0.w, a1.x, a1.y, a1.z, a1.w};
        #pragma unroll
        for (int j = 0; j < 4; j++) {
            float2 p; p.x = v[2 * j]; p.y = v[2 * j + 1];
            ((float2*)xtf)[((pk >> 1) + j) * 33 + pb] = p;
        }
    }
    float4 pxa = *(const float4*)(xrow + (size_t)Iq);
    float4 pxb = *(const float4*)(xrow + (size_t)Iq + 4);

    // ================= recurrent loop =================
    for (int t = 0; t < Sq; t++) {
        // ---- stage h(t-1) into paired SMEM ----
        if (t == 0) {
            for (int i = tid; i < Hq * GB; i += NTHR) {
                int b = i >> 8, u = i & 255;
                hsf[((u >> 1) * 33 + b) * 2 + (u & 1)] = 0.f;
            }
        } else {
            const int b2 = tid >> 4;
            const int u0 = (tid & 15) * 16;
            const float* ep = d_enc + (size_t)(t - 1) * Bq * Hq + (size_t)(gb0 + b2) * Hq + u0;
            float4 h0 = *(const float4*)(ep);
            float4 h1 = *(const float4*)(ep + 4);
            float4 h2 = *(const float4*)(ep + 8);
            float4 h3 = *(const float4*)(ep + 12);
            const float hv[16] = {h0.x,h0.y,h0.z,h0.w, h1.x,h1.y,h1.z,h1.w,
                                  h2.x,h2.y,h2.z,h2.w, h3.x,h3.y,h3.z,h3.w};
            #pragma unroll
            for (int j = 0; j < 8; j++) {
                float2 p; p.x = hv[2 * j]; p.y = hv[2 * j + 1];
                ((float2*)hsf)[((u0 >> 1) + j) * 33 + b2] = p;
            }
        }
        __syncthreads();

        // ---- P1: warp (rg, bh): score row rg + gh rows 6rg..6rg+5 for 16 batches,
        //      half-warps split K; combine via shfl_xor(16) ----
        {
            const int R = 6 * rg;
            u64 sacc = 0ull, a0 = 0ull, a1 = 0ull, a2 = 0ull, a3 = 0ull, a4 = 0ull, a5 = 0ull;

            const u64* wax = (const u64*)(sm + O_WAX) + rg * 66 + sub * 34;
            const int kx = sub * 32;
            #pragma unroll 4
            for (int i = 0; i < 32; i += 2) {
                u64 x0 = xt64[(kx + i) * 33 + bb1];
                u64 x1 = xt64[(kx + i + 1) * 33 + bb1];
                ulonglong2 wv = *(const ulonglong2*)(wax + i);
                fma2(sacc, wv.x, x0); fma2(sacc, wv.y, x1);
            }
            const u64* wah = (const u64*)(sm + O_WAH) + rg * 130 + sub * 66;
            const u64* wg  = (const u64*)(sm + O_WHH) + R * 130 + sub * 66;
            const int kh = sub * 64;
            #pragma unroll 4
            for (int i = 0; i < 64; i += 2) {
                u64 h0 = hs64[(kh + i) * 33 + bb1];
                u64 h1 = hs64[(kh + i + 1) * 33 + bb1];
                ulonglong2 wv;
                wv = *(const ulonglong2*)(wah + i);       fma2(sacc, wv.x, h0); fma2(sacc, wv.y, h1);
                wv = *(const ulonglong2*)(wg + i);        fma2(a0, wv.x, h0);   fma2(a0, wv.y, h1);
                wv = *(const ulonglong2*)(wg + 130 + i);  fma2(a1, wv.x, h0);   fma2(a1, wv.y, h1);
                wv = *(const ulonglong2*)(wg + 260 + i);  fma2(a2, wv.x, h0);   fma2(a2, wv.y, h1);
                wv = *(const ulonglong2*)(wg + 390 + i);  fma2(a3, wv.x, h0);   fma2(a3, wv.y, h1);
                wv = *(const ulonglong2*)(wg + 520 + i);  fma2(a4, wv.x, h0);   fma2(a4, wv.y, h1);
                wv = *(const ulonglong2*)(wg + 650 + i);  fma2(a5, wv.x, h0);   fma2(a5, wv.y, h1);
            }
            float s  = f2sum(sacc, 0.f); s  += __shfl_xor_sync(0xffffffffu, s, 16);
            float g0 = f2sum(a0, 0.f);   g0 += __shfl_xor_sync(0xffffffffu, g0, 16);
            float g1 = f2sum(a1, 0.f);   g1 += __shfl_xor_sync(0xffffffffu, g1, 16);
            float g2 = f2sum(a2, 0.f);   g2 += __shfl_xor_sync(0xffffffffu, g2, 16);
            float g3 = f2sum(a3, 0.f);   g3 += __shfl_xor_sync(0xffffffffu, g3, 16);
            float g4 = f2sum(a4, 0.f);   g4 += __shfl_xor_sync(0xffffffffu, g4, 16);
            float g5 = f2sum(a5, 0.f);   g5 += __shfl_xor_sync(0xffffffffu, g5, 16);
            if (sub == 0) {
                ghs[(R + 0) * 33 + bb1] = g0 + bhh_s[R + 0];
                ghs[(R + 1) * 33 + bb1] = g1 + bhh_s[R + 1];
                ghs[(R + 2) * 33 + bb1] = g2 + bhh_s[R + 2];
                ghs[(R + 3) * 33 + bb1] = g3 + bhh_s[R + 3];
                ghs[(R + 4) * 33 + bb1] = g4 + bhh_s[R + 4];
                ghs[(R + 5) * 33 + bb1] = g5 + bhh_s[R + 5];
                __stcg(&d_scores[(gb0 + bb1) * Iq + 8 * rr + rg],
                       ftanh(s + ba_s[rg]));
            }
        }
        group_barrier(grp, want);   // scores visible group-wide

        // ---- P2: softmax + xw, 2 batches per warp ----
        #pragma unroll
        for (int bi = 0; bi < 2; bi++) {
            int b = 2 * wrp + bi;
            const float* sp = d_scores + (size_t)(gb0 + b) * Iq;
            float e0 = __expf(__ldcg(sp + lane));
            float e1 = __expf(__ldcg(sp + lane + 32));
            float e2 = __expf(__ldcg(sp + lane + 64));
            float e3 = __expf(__ldcg(sp + lane + 96));
            float s = e0 + e1 + e2 + e3;
            #pragma unroll
            for (int off = 16; off; off >>= 1) s += __shfl_xor_sync(0xffffffffu, s, off);
            float inv = 1.f / s;
            int k = lane;
            xwf[((k >> 1) * 33 + b) * 2 + (k & 1)] = e0 * inv * xtf[((k >> 1) * 33 + b) * 2 + (k & 1)];
            k = lane + 32;
            xwf[((k >> 1) * 33 + b) * 2 + (k & 1)] = e1 * inv * xtf[((k >> 1) * 33 + b) * 2 + (k & 1)];
            k = lane + 64;
            xwf[((k >> 1) * 33 + b) * 2 + (k & 1)] = e2 * inv * xtf[((k >> 1) * 33 + b) * 2 + (k & 1)];
            k = lane + 96;
            xwf[((k >> 1) * 33 + b) * 2 + (k & 1)] = e3 * inv * xtf[((k >> 1) * 33 + b) * 2 + (k & 1)];
        }
        __syncthreads();   // xw ready; all xtf(t) reads complete

        // ---- commit prefetched x(t+1); prefetch x(t+2) ----
        if (t + 1 < Sq) {
            const float v[8] = {pxa.x, pxa.y, pxa.z, pxa.w, pxb.x, pxb.y, pxb.z, pxb.w};
            #pragma unroll
            for (int j = 0; j < 4; j++) {
                float2 p; p.x = v[2 * j]; p.y = v[2 * j + 1];
                ((float2*)xtf)[((pk >> 1) + j) * 33 + pb] = p;
            }
            if (t + 2 < Sq) {
                pxa = *(const float4*)(xrow + (size_t)(t + 2) * Iq);
                pxb = *(const float4*)(xrow + (size_t)(t + 2) * Iq + 4);
            }
        }

        // ---- P3: gi rows 6rg..6rg+5 for 16 batches, K-split halves ----
        {
            const int R = 6 * rg;
            const u64* wi = (const u64*)(sm + O_WIH) + R * 66 + sub * 34;
            u64 c0 = 0ull, c1 = 0ull, c2 = 0ull, c3 = 0ull, c4 = 0ull, c5 = 0ull;
            const int kx = sub * 32;
            #pragma unroll 4
            for (int i = 0; i < 32; i += 2) {
                u64 x0 = xw64[(kx + i) * 33 + bb1];
                u64 x1 = xw64[(kx + i + 1) * 33 + bb1];
                ulonglong2 wv;
                wv = *(const ulonglong2*)(wi + i);        fma2(c0, wv.x, x0); fma2(c0, wv.y, x1);
                wv = *(const ulonglong2*)(wi + 66 + i);   fma2(c1, wv.x, x0); fma2(c1, wv.y, x1);
                wv = *(const ulonglong2*)(wi + 132 + i);  fma2(c2, wv.x, x0); fma2(c2, wv.y, x1);
                wv = *(const ulonglong2*)(wi + 198 + i);  fma2(c3, wv.x, x0); fma2(c3, wv.y, x1);
                wv = *(const ulonglong2*)(wi + 264 + i);  fma2(c4, wv.x, x0); fma2(c4, wv.y, x1);
                wv = *(const ulonglong2*)(wi + 330 + i);  fma2(c5, wv.x, x0); fma2(c5, wv.y, x1);
            }
            float q0 = f2sum(c0, 0.f); q0 += __shfl_xor_sync(0xffffffffu, q0, 16);
            float q1 = f2sum(c1, 0.f); q1 += __shfl_xor_sync(0xffffffffu, q1, 16);
            float q2 = f2sum(c2, 0.f); q2 += __shfl_xor_sync(0xffffffffu, q2, 16);
            float q3 = f2sum(c3, 0.f); q3 += __shfl_xor_sync(0xffffffffu, q3, 16);
            float q4 = f2sum(c4, 0.f); q4 += __shfl_xor_sync(0xffffffffu, q4, 16);
            float q5 = f2sum(c5, 0.f); q5 += __shfl_xor_sync(0xffffffffu, q5, 16);
            if (sub == 0) {
                gis[(R + 0) * 33 + bb1] = q0 + bih_s[R + 0];
                gis[(R + 1) * 33 + bb1] = q1 + bih_s[R + 1];
                gis[(R + 2) * 33 + bb1] = q2 + bih_s[R + 2];
                gis[(R + 3) * 33 + bb1] = q3 + bih_s[R + 3];
                gis[(R + 4) * 33 + bb1] = q4 + bih_s[R + 4];
                gis[(R + 5) * 33 + bb1] = q5 + bih_s[R + 5];
            }
        }
        __syncthreads();

        // ---- gates + h_new ----
        {
            int u = tid & 15;
            int b = tid >> 4;
            float r = fsig(gis[u * 33 + b] + ghs[u * 33 + b]);
            float z = fsig(gis[(16 + u) * 33 + b] + ghs[(16 + u) * 33 + b]);
            float n = ftanh(gis[(32 + u) * 33 + b] + r * ghs[(32 + u) * 33 + b]);
            int ug = 16 * rr + u;
            float hp = hsf[((ug >> 1) * 33 + b) * 2 + (ug & 1)];
            float hn = (1.f - z) * n + z * hp;
            d_enc[((size_t)t * Bq + gb0 + b) * Hq + ug] = hn;
        }
        group_barrier(grp, want);   // h(t) visible group-wide
    }

    // ================= temporal attention + FC (2 batches/CTA) =================
    float* wts = xtf;     // 256 floats
    float* ess = gis;     // 512 floats
    float* prt = ghs;     // 512 floats
    if (tid < Hq) wts[tid] = W_t[tid];
    const float btv = b_t[0];
    const float bfv = b_f[0];
    __syncthreads();

    for (int bi = 0; bi < 2; bi++) {
        int bb = gb0 + 2 * rr + bi;

        for (int tt = wrp; tt < Sq; tt += 16) {
            const float* er = d_enc + ((size_t)tt * Bq + bb) * Hq;
            float s = 0.f;
            #pragma unroll
            for (int j = 0; j < 8; j++) s += er[lane + 32 * j] * wts[lane + 32 * j];
            #pragma unroll
            for (int off = 16; off; off >>= 1) s += __shfl_xor_sync(0xffffffffu, s, off);
            if (lane == 0) ess[tt] = __expf(ftanh(s + btv));
        }
        __syncthreads();

        float pp = ess[tid];
        #pragma unroll
        for (int off = 16; off; off >>= 1) pp += __shfl_xor_sync(0xffffffffu, pp, off);
        if (lane == 0) red[wrp] = pp;
        __syncthreads();
        float denom = 0.f;
        #pragma unroll
        for (int j = 0; j < 16; j++) denom += red[j];

        {
            int h = tid & 255, half = tid >> 8;
            const float* eb = d_enc + ((size_t)(half * 256) * Bq + bb) * Hq + h;
            const float* ep = ess + half * 256;
            float acc = 0.f;
            #pragma unroll 4
            for (int tt = 0; tt < 256; tt++)
                acc += ep[tt] * eb[(size_t)tt * Bq * Hq];
            prt[tid] = acc;
        }
        __syncthreads();

        if (tid < Hq) {
            float ctx = (prt[tid] + prt[tid + 256]) / denom;
            float part = ctx * W_f[tid];
            #pragma unroll
            for (int off = 16; off; off >>= 1) part += __shfl_xor_sync(0xffffffffu, part, off);
            if (lane == 0) red[16 + wrp] = part;
        }
        __syncthreads();
        if (tid == 0) {
            float lg = bfv;
            #pragma unroll
            for (int j = 0; j < 8; j++) lg += red[16 + j];
            out[bb] = 1.f / (1.f + __expf(-lg));
        }
        __syncthreads();
    }
}

extern "C" void kernel_launch(void* const* d_in, const int* in_sizes, int n_in,
                              void* d_out, int out_size)
{
    const float* x    = (const float*)d_in[0];
    const float* W_a  = (const float*)d_in[1];
    const float* b_a  = (const float*)d_in[2];
    const float* W_ih = (const float*)d_in[3];
    const float* b_ih = (const float*)d_in[4];
    const float* W_hh = (const float*)d_in[5];
    const float* b_hh = (const float*)d_in[6];
    const float* W_t  = (const float*)d_in[7];
    const float* b_t  = (const float*)d_in[8];
    const float* W_f  = (const float*)d_in[9];
    const float* b_f  = (const float*)d_in[10];

    const size_t smem_bytes = (size_t)SMEM_FLOATS * sizeof(float);   // 168608
    cudaFuncSetAttribute(da_rnn_kernel, cudaFuncAttributeMaxDynamicSharedMemorySize,
                         (int)smem_bytes);
    da_rnn_kernel<<<NCTA, NTHR, smem_bytes>>>(x, W_a, b_a, W_ih, b_ih, W_hh, b_hh,
                                              W_t, b_t, W_f, b_f, (float*)d_out);
}

// round 16
// speedup vs baseline: 1.4379x; 1.2432x over previous
#include <cuda_runtime.h>
#include <math.h>
#include <stdint.h>

#define Bq 256
#define Sq 512
#define Iq 128
#define Hq 256
#define CPG 16      // CTAs per group
#define NGRP 8      // groups
#define GB 32       // batches per group
#define NCTA 128
#define NTHR 512

typedef unsigned long long u64;

// ---- global scratch ----
__device__ float d_enc[(size_t)Sq * Bq * Hq];   // [S][B][H]
__device__ float d_scores[Bq * Iq];             // reused every step -> L1-bypass access
__device__ int   g_cnt[NGRP];
__device__ int   g_phase[NGRP];

// ------------------------------- helpers -----------------------------------
__device__ __forceinline__ int ld_acq(const int* p) {
    int v;
    asm volatile("ld.acquire.gpu.b32 %0, [%1];" : "=r"(v) : "l"(p) : "memory");
    return v;
}
__device__ __forceinline__ int atom_add_release(int* p, int v) {
    int old;
    asm volatile("atom.release.gpu.global.add.s32 %0, [%1], %2;"
                 : "=r"(old) : "l"(p), "r"(v) : "memory");
    return old;
}
__device__ __forceinline__ void red_release_add(int* p, int v) {
    asm volatile("red.release.gpu.global.add.s32 [%0], %1;" :: "l"(p), "r"(v) : "memory");
}
__device__ __forceinline__ void st_relaxed(int* p, int v) {
    asm volatile("st.relaxed.gpu.global.s32 [%0], %1;" :: "l"(p), "r"(v) : "memory");
}
__device__ __forceinline__ void fma2(u64& d, u64 a, u64 b) {
    asm("fma.rn.f32x2 %0, %1, %2, %0;" : "+l"(d) : "l"(a), "l"(b));
}
__device__ __forceinline__ u64 dupf(float f) {            // {f, f}
    u64 r;
    asm("mov.b64 %0, {%1,%1};" : "=l"(r) : "f"(f));
    return r;
}
__device__ __forceinline__ u64 addf2(u64 a, u64 b) {      // packed f32x2 add
    u64 d;
    asm("add.rn.f32x2 %0, %1, %2;" : "=l"(d) : "l"(a), "l"(b));
    return d;
}
__device__ __forceinline__ u64 shflx16(u64 v) {
    return (u64)__shfl_xor_sync(0xffffffffu, (unsigned long long)v, 16);
}
__device__ __forceinline__ float fsig(float x)  { return 1.f / (1.f + __expf(-x)); }
__device__ __forceinline__ float ftanh(float x) { return 1.f - 2.f / (__expf(2.f * x) + 1.f); }

// Fence-free group barrier pieces (validated R11-R13). Caller supplies the
// surrounding __syncthreads; arrive/wait split lets us hide work under the poll.
__device__ __forceinline__ void gb_arrive(int g, int& want) {
    want++;
    int old = atom_add_release(&g_cnt[g], 1);
    if (old == CPG - 1) {
        st_relaxed(&g_cnt[g], 0);
        red_release_add(&g_phase[g], 1);
    }
}
__device__ __forceinline__ void gb_wait(int g, int want) {
    while (ld_acq(&g_phase[g]) < want) { }
}

// SMEM layout (float offsets, all even). Activations are batch-pair packed:
//   h  u64 at [k*17 + (k>>4) + p]  = {h[k][p], h[k][p+16]}
//   x  u64 at [k*17 + (k>>3) + p]  = {x[k][p], x[k][p+16]}
#define O_WHH  0        // 48*256 = 12288
#define O_WIH  12288    // 48*128 = 6144
#define O_WAH  18432    // 8*256  = 2048
#define O_WAX  20480    // 8*128  = 1024
#define O_BA   21504    // 8
#define O_BIH  21512    // 48
#define O_BHH  21560    // 48
#define O_HS   21608    // 4368 u64 = 8736 floats
#define O_XTS  30344    // 2192 u64 = 4384
#define O_XWS  34728    // 4384
#define O_GISA 39112    // 816 u64 = 1632
#define O_GISB 40744    // 1632
#define O_GHSA 42376    // 1632
#define O_GHSB 44008    // 1632
#define O_PSC  45640    // 256 u64 = 512
#define O_PSX  46152    // 512
#define O_RED  46664    // 32
#define SMEM_FLOATS 46696   // 186,784 bytes

#define HIDX(k,b) ((((k)*17 + ((k)>>4) + ((b)&15))*2) + ((b)>>4))
#define XIDX(k,b) ((((k)*17 + ((k)>>3) + ((b)&15))*2) + ((b)>>4))

extern "C" __global__ void __launch_bounds__(NTHR)
da_rnn_kernel(const float* __restrict__ x,
              const float* __restrict__ W_a,  const float* __restrict__ b_a,
              const float* __restrict__ W_ih, const float* __restrict__ b_ih,
              const float* __restrict__ W_hh, const float* __restrict__ b_hh,
              const float* __restrict__ W_t,  const float* __restrict__ b_t,
              const float* __restrict__ W_f,  const float* __restrict__ b_f,
              float* __restrict__ out)
{
    extern __shared__ float sm[];
    float* Whh_s = sm + O_WHH;
    float* Wih_s = sm + O_WIH;
    float* Wah_s = sm + O_WAH;
    float* Wax_s = sm + O_WAX;
    float* ba_s  = sm + O_BA;
    float* bih_s = sm + O_BIH;
    float* bhh_s = sm + O_BHH;
    float* hsf   = sm + O_HS;
    float* xtf   = sm + O_XTS;
    float* xwf   = sm + O_XWS;
    float* gisAf = sm + O_GISA;
    float* gisBf = sm + O_GISB;
    float* ghsAf = sm + O_GHSA;
    float* ghsBf = sm + O_GHSB;
    float* red   = sm + O_RED;
    const u64* hs64 = (const u64*)hsf;
    const u64* xt64 = (const u64*)xtf;
    const u64* xw64 = (const u64*)xwf;
    u64* gisA64 = (u64*)gisAf;
    u64* gisB64 = (u64*)gisBf;
    u64* ghsA64 = (u64*)ghsAf;
    u64* ghsB64 = (u64*)ghsBf;
    u64* psc64  = (u64*)(sm + O_PSC);
    u64* psx64  = (u64*)(sm + O_PSX);

    const int tid  = threadIdx.x;
    const int grp  = blockIdx.x >> 4;
    const int rr   = blockIdx.x & 15;
    const int gb0  = grp * GB;
    const int lane = tid & 31;
    const int wrp  = tid >> 5;            // 0..15
    const int sub  = lane >> 4;           // K sub-half within warp
    const int p    = lane & 15;           // batch-pair index
    const int rg   = wrp >> 1;            // row group / score row 0..7
    const int ksel = wrp & 1;             // K half

    // ---- load weight slice into SMEM (plain k-major float) ----
    for (int i = tid; i < 48 * 256; i += NTHR) {
        int l = i >> 8, k = i & 255;
        int grow = (l >> 4) * Hq + 16 * rr + (l & 15);
        Whh_s[i] = W_hh[grow * Hq + k];
    }
    for (int i = tid; i < 48 * 128; i += NTHR) {
        int l = i >> 7, k = i & 127;
        int grow = (l >> 4) * Hq + 16 * rr + (l & 15);
        Wih_s[i] = W_ih[grow * Iq + k];
    }
    for (int i = tid; i < 8 * 256; i += NTHR) {
        int r = i >> 8, k = i & 255;
        Wah_s[i] = W_a[(8 * rr + r) * 384 + 128 + k];
    }
    for (int i = tid; i < 8 * 128; i += NTHR) {
        int r = i >> 7, k = i & 127;
        Wax_s[i] = W_a[(8 * rr + r) * 384 + k];
    }
    if (tid < 8) ba_s[tid] = b_a[8 * rr + tid];
    if (tid < 48) {
        int grow = (tid >> 4) * Hq + 16 * rr + (tid & 15);
        bih_s[tid] = b_ih[grow];
        bhh_s[tid] = b_hh[grow];
    }

    int want = 0;
    if (tid == 0) want = ld_acq(&g_phase[grp]);

    // ---- x pipeline: thread owns (batch pb, k-range pk..pk+7) ----
    const int pb = tid >> 4;            // 0..31
    const int pk = (tid & 15) * 8;      // 0..120
    const float* xrow = x + ((size_t)(gb0 + pb) * Sq) * Iq + pk;

    // prologue: xtf <- x(0); px <- x(1)
    {
        float4 a0 = *(const float4*)(xrow);
        float4 a1 = *(const float4*)(xrow + 4);
        const float v[8] = {a0.x, a0.y, a0.z, a0.w, a1.x, a1.y, a1.z, a1.w};
        #pragma unroll
        for (int j = 0; j < 8; j++) xtf[XIDX(pk + j, pb)] = v[j];
    }
    float4 pxa = *(const float4*)(xrow + (size_t)Iq);
    float4 pxb = *(const float4*)(xrow + (size_t)Iq + 4);
    __syncthreads();

    // prologue psx(0): score x-part for t=0
    {
        const int kq = ksel * 64 + sub * 32;
        const float* wax = Wax_s + rg * 128;
        u64 xacc = 0ull;
        #pragma unroll 4
        for (int i = 0; i < 16; i++) {
            int k = kq + 2 * i;
            u64 x0 = xt64[k * 17 + (k >> 3) + p];
            u64 x1 = xt64[(k + 1) * 17 + ((k + 1) >> 3) + p];
            float2 f = *(const float2*)(wax + k);
            fma2(xacc, dupf(f.x), x0);
            fma2(xacc, dupf(f.y), x1);
        }
        xacc = addf2(xacc, shflx16(xacc));
        if (sub == 0) psx64[wrp * 16 + p] = xacc;
    }

    // ================= recurrent loop =================
    for (int t = 0; t < Sq; t++) {
        // ---- stage h(t-1) into batch-pair SMEM ----
        if (t == 0) {
            for (int i = tid; i < 8736; i += NTHR) hsf[i] = 0.f;
        } else {
            const int b2 = tid >> 4;
            const int u0 = (tid & 15) * 16;
            const float* ep = d_enc + (size_t)(t - 1) * Bq * Hq + (size_t)(gb0 + b2) * Hq + u0;
            float4 h0 = *(const float4*)(ep);
            float4 h1 = *(const float4*)(ep + 4);
            float4 h2 = *(const float4*)(ep + 8);
            float4 h3 = *(const float4*)(ep + 12);
            const float hv[16] = {h0.x,h0.y,h0.z,h0.w, h1.x,h1.y,h1.z,h1.w,
                                  h2.x,h2.y,h2.z,h2.w, h3.x,h3.y,h3.z,h3.w};
            #pragma unroll
            for (int j = 0; j < 16; j++) hsf[HIDX(u0 + j, b2)] = hv[j];
        }
        __syncthreads();

        // ---- P1: warp (rg,ksel): gh rows 6rg..6rg+5 + score row rg (h-part),
        //      batch-pair lanes, sub splits the k-quarter ----
        {
            const int R = 6 * rg;
            const int kq = ksel * 128 + sub * 64;
            const float* whh = Whh_s + R * 256;
            const float* wah = Wah_s + rg * 256;
            u64 a0 = 0ull, a1 = 0ull, a2 = 0ull, a3 = 0ull, a4 = 0ull, a5 = 0ull, sacc = 0ull;
            #pragma unroll 2
            for (int i = 0; i < 32; i++) {
                int k = kq + 2 * i;
                u64 h0 = hs64[k * 17 + (k >> 4) + p];
                u64 h1 = hs64[(k + 1) * 17 + ((k + 1) >> 4) + p];
                float2 f;
                f = *(const float2*)(whh + k);
                fma2(a0, dupf(f.x), h0); fma2(a0, dupf(f.y), h1);
                f = *(const float2*)(whh + 256 + k);
                fma2(a1, dupf(f.x), h0); fma2(a1, dupf(f.y), h1);
                f = *(const float2*)(whh + 512 + k);
                fma2(a2, dupf(f.x), h0); fma2(a2, dupf(f.y), h1);
                f = *(const float2*)(whh + 768 + k);
                fma2(a3, dupf(f.x), h0); fma2(a3, dupf(f.y), h1);
                f = *(const float2*)(whh + 1024 + k);
                fma2(a4, dupf(f.x), h0); fma2(a4, dupf(f.y), h1);
                f = *(const float2*)(whh + 1280 + k);
                fma2(a5, dupf(f.x), h0); fma2(a5, dupf(f.y), h1);
                f = *(const float2*)(wah + k);
                fma2(sacc, dupf(f.x), h0); fma2(sacc, dupf(f.y), h1);
            }
            a0 = addf2(a0, shflx16(a0));
            a1 = addf2(a1, shflx16(a1));
            a2 = addf2(a2, shflx16(a2));
            a3 = addf2(a3, shflx16(a3));
            a4 = addf2(a4, shflx16(a4));
            a5 = addf2(a5, shflx16(a5));
            sacc = addf2(sacc, shflx16(sacc));
            if (sub == 0) {
                u64* gX = ksel ? ghsB64 : ghsA64;
                gX[(R + 0) * 17 + p] = a0;
                gX[(R + 1) * 17 + p] = a1;
                gX[(R + 2) * 17 + p] = a2;
                gX[(R + 3) * 17 + p] = a3;
                gX[(R + 4) * 17 + p] = a4;
                gX[(R + 5) * 17 + p] = a5;
                psc64[wrp * 16 + p] = sacc;
            }
        }
        __syncthreads();

        // ---- finalize scores: combine psc (h-part quarters) + psx (x-part) ----
        if (tid < 128) {
            int r = tid >> 4, pp = tid & 15;
            const float2* pc = (const float2*)psc64;
            const float2* px = (const float2*)psx64;
            float2 c0 = pc[(2 * r) * 16 + pp];
            float2 c1 = pc[(2 * r + 1) * 16 + pp];
            float2 x0 = px[(2 * r) * 16 + pp];
            float2 x1 = px[(2 * r + 1) * 16 + pp];
            float lo = c0.x + c1.x + x0.x + x1.x + ba_s[r];
            float hi = c0.y + c1.y + x0.y + x1.y + ba_s[r];
            __stcg(&d_scores[(gb0 + pp) * Iq + 8 * rr + r], ftanh(lo));
            __stcg(&d_scores[(gb0 + pp + 16) * Iq + 8 * rr + r], ftanh(hi));
        }
        // ---- scores barrier ----
        __syncthreads();
        if (tid == 0) { gb_arrive(grp, want); gb_wait(grp, want); }
        __syncthreads();

        // ---- P2: softmax + xw, 2 batches per warp ----
        #pragma unroll
        for (int bi = 0; bi < 2; bi++) {
            int b = 2 * wrp + bi;
            const float* sp = d_scores + (size_t)(gb0 + b) * Iq;
            float e0 = __expf(__ldcg(sp + lane));
            float e1 = __expf(__ldcg(sp + lane + 32));
            float e2 = __expf(__ldcg(sp + lane + 64));
            float e3 = __expf(__ldcg(sp + lane + 96));
            float s = e0 + e1 + e2 + e3;
            #pragma unroll
            for (int off = 16; off; off >>= 1) s += __shfl_xor_sync(0xffffffffu, s, off);
            float inv = 1.f / s;
            int k = lane;
            xwf[XIDX(k, b)] = e0 * inv * xtf[XIDX(k, b)];
            k = lane + 32;
            xwf[XIDX(k, b)] = e1 * inv * xtf[XIDX(k, b)];
            k = lane + 64;
            xwf[XIDX(k, b)] = e2 * inv * xtf[XIDX(k, b)];
            k = lane + 96;
            xwf[XIDX(k, b)] = e3 * inv * xtf[XIDX(k, b)];
        }
        __syncthreads();   // xw ready; all xtf(t) reads complete

        // ---- commit prefetched x(t+1); prefetch x(t+2) ----
        if (t + 1 < Sq) {
            const float v[8] = {pxa.x, pxa.y, pxa.z, pxa.w, pxb.x, pxb.y, pxb.z, pxb.w};
            #pragma unroll
            for (int j = 0; j < 8; j++) xtf[XIDX(pk + j, pb)] = v[j];
            if (t + 2 < Sq) {
                pxa = *(const float4*)(xrow + (size_t)(t + 2) * Iq);
                pxb = *(const float4*)(xrow + (size_t)(t + 2) * Iq + 4);
            }
        }

        // ---- P3: gi rows 6rg..6rg+5, batch-pair, sub splits k-quarter ----
        {
            const int R = 6 * rg;
            const int kq = ksel * 64 + sub * 32;
            const float* wih = Wih_s + R * 128;
            u64 c0 = 0ull, c1 = 0ull, c2 = 0ull, c3 = 0ull, c4 = 0ull, c5 = 0ull;
            #pragma unroll 2
            for (int i = 0; i < 16; i++) {
                int k = kq + 2 * i;
                u64 x0 = xw64[k * 17 + (k >> 3) + p];
                u64 x1 = xw64[(k + 1) * 17 + ((k + 1) >> 3) + p];
                float2 f;
                f = *(const float2*)(wih + k);
                fma2(c0, dupf(f.x), x0); fma2(c0, dupf(f.y), x1);
                f = *(const float2*)(wih + 128 + k);
                fma2(c1, dupf(f.x), x0); fma2(c1, dupf(f.y), x1);
                f = *(const float2*)(wih + 256 + k);
                fma2(c2, dupf(f.x), x0); fma2(c2, dupf(f.y), x1);
                f = *(const float2*)(wih + 384 + k);
                fma2(c3, dupf(f.x), x0); fma2(c3, dupf(f.y), x1);
                f = *(const float2*)(wih + 512 + k);
                fma2(c4, dupf(f.x), x0); fma2(c4, dupf(f.y), x1);
                f = *(const float2*)(wih + 640 + k);
                fma2(c5, dupf(f.x), x0); fma2(c5, dupf(f.y), x1);
            }
            c0 = addf2(c0, shflx16(c0));
            c1 = addf2(c1, shflx16(c1));
            c2 = addf2(c2, shflx16(c2));
            c3 = addf2(c3, shflx16(c3));
            c4 = addf2(c4, shflx16(c4));
            c5 = addf2(c5, shflx16(c5));
            if (sub == 0) {
                u64* gX = ksel ? gisB64 : gisA64;
                gX[(R + 0) * 17 + p] = c0;
                gX[(R + 1) * 17 + p] = c1;
                gX[(R + 2) * 17 + p] = c2;
                gX[(R + 3) * 17 + p] = c3;
                gX[(R + 4) * 17 + p] = c4;
                gX[(R + 5) * 17 + p] = c5;
            }
        }
        __syncthreads();

        // ---- gates + h_new ----
        {
            int u = tid & 15;
            int b = tid >> 4;
            int pq = b & 15, hb = b >> 4;
            #define GX(l) (((l) * 17 + pq) * 2 + hb)
            float gi_r = gisAf[GX(u)] + gisBf[GX(u)] + bih_s[u];
            float gh_r = ghsAf[GX(u)] + ghsBf[GX(u)] + bhh_s[u];
            float gi_z = gisAf[GX(16 + u)] + gisBf[GX(16 + u)] + bih_s[16 + u];
            float gh_z = ghsAf[GX(16 + u)] + ghsBf[GX(16 + u)] + bhh_s[16 + u];
            float gi_n = gisAf[GX(32 + u)] + gisBf[GX(32 + u)] + bih_s[32 + u];
            float gh_n = ghsAf[GX(32 + u)] + ghsBf[GX(32 + u)] + bhh_s[32 + u];
            #undef GX
            float r = fsig(gi_r + gh_r);
            float z = fsig(gi_z + gh_z);
            float n = ftanh(gi_n + r * gh_n);
            int ug = 16 * rr + u;
            float hp = hsf[HIDX(ug, b)];
            float hn = (1.f - z) * n + z * hp;
            d_enc[((size_t)t * Bq + gb0 + b) * Hq + ug] = hn;
        }
        // ---- h barrier with hidden work: psx(t+1) under the poll ----
        __syncthreads();
        if (tid == 0) gb_arrive(grp, want);
        if (t + 1 < Sq) {          // score x-part for t+1 (xtf already = x(t+1))
            const int kq = ksel * 64 + sub * 32;
            const float* wax = Wax_s + rg * 128;
            u64 xacc = 0ull;
            #pragma unroll 4
            for (int i = 0; i < 16; i++) {
                int k = kq + 2 * i;
                u64 x0 = xt64[k * 17 + (k >> 3) + p];
                u64 x1 = xt64[(k + 1) * 17 + ((k + 1) >> 3) + p];
                float2 f = *(const float2*)(wax + k);
                fma2(xacc, dupf(f.x), x0);
                fma2(xacc, dupf(f.y), x1);
            }
            xacc = addf2(xacc, shflx16(xacc));
            if (sub == 0) psx64[wrp * 16 + p] = xacc;
        }
        if (tid == 0) gb_wait(grp, want);
        __syncthreads();
    }

    // ================= temporal attention + FC (2 batches/CTA) =================
    float* wts = xtf;            // 256 floats (region reuse, linear)
    float* ess = gisAf;          // 512 floats
    float* prt = ghsAf;          // 512 floats
    if (tid < Hq) wts[tid] = W_t[tid];
    const float btv = b_t[0];
    const float bfv = b_f[0];
    __syncthreads();

    for (int bi = 0; bi < 2; bi++) {
        int bb = gb0 + 2 * rr + bi;

        for (int tt = wrp; tt < Sq; tt += 16) {
            const float* er = d_enc + ((size_t)tt * Bq + bb) * Hq;
            float s = 0.f;
            #pragma unroll
            for (int j = 0; j < 8; j++) s += er[lane + 32 * j] * wts[lane + 32 * j];
            #pragma unroll
            for (int off = 16; off; off >>= 1) s += __shfl_xor_sync(0xffffffffu, s, off);
            if (lane == 0) ess[tt] = __expf(ftanh(s + btv));
        }
        __syncthreads();

        float pp = ess[tid];
        #pragma unroll
        for (int off = 16; off; off >>= 1) pp += __shfl_xor_sync(0xffffffffu, pp, off);
        if (lane == 0) red[wrp] = pp;
        __syncthreads();
        float denom = 0.f;
        #pragma unroll
        for (int j = 0; j < 16; j++) denom += red[j];

        {
            int h = tid & 255, half = tid >> 8;
            const float* eb = d_enc + ((size_t)(half * 256) * Bq + bb) * Hq + h;
            const float* ep = ess + half * 256;
            float acc = 0.f;
            #pragma unroll 4
            for (int tt = 0; tt < 256; tt++)
                acc += ep[tt] * eb[(size_t)tt * Bq * Hq];
            prt[tid] = acc;
        }
        __syncthreads();

        if (tid < Hq) {
            float ctx = (prt[tid] + prt[tid + 256]) / denom;
            float part = ctx * W_f[tid];
            #pragma unroll
            for (int off = 16; off; off >>= 1) part += __shfl_xor_sync(0xffffffffu, part, off);
            if (lane == 0) red[16 + wrp] = part;
        }
        __syncthreads();
        if (tid == 0) {
            float lg = bfv;
            #pragma unroll
            for (int j = 0; j < 8; j++) lg += red[16 + j];
            out[bb] = 1.f / (1.f + __expf(-lg));
        }
        __syncthreads();
    }
}

extern "C" void kernel_launch(void* const* d_in, const int* in_sizes, int n_in,
                              void* d_out, int out_size)
{
    const float* x    = (const float*)d_in[0];
    const float* W_a  = (const float*)d_in[1];
    const float* b_a  = (const float*)d_in[2];
    const float* W_ih = (const float*)d_in[3];
    const float* b_ih = (const float*)d_in[4];
    const float* W_hh = (const float*)d_in[5];
    const float* b_hh = (const float*)d_in[6];
    const float* W_t  = (const float*)d_in[7];
    const float* b_t  = (const float*)d_in[8];
    const float* W_f  = (const float*)d_in[9];
    const float* b_f  = (const float*)d_in[10];

    const size_t smem_bytes = (size_t)SMEM_FLOATS * sizeof(float);   // 186784
    cudaFuncSetAttribute(da_rnn_kernel, cudaFuncAttributeMaxDynamicSharedMemorySize,
                         (int)smem_bytes);
    da_rnn_kernel<<<NCTA, NTHR, smem_bytes>>>(x, W_a, b_a, W_ih, b_ih, W_hh, b_hh,
                                              W_t, b_t, W_f, b_f, (float*)d_out);
}